// round 3
// baseline (speedup 1.0000x reference)
#include <cuda_runtime.h>

#define NN 100000
#define NE 3200000
#define NF 256
#define NH 16

// Scratch (__device__ globals — no runtime allocation)
__device__ __align__(16) float g_gbuf[NN * NH];   // per-node message features (g = h * dinv)
__device__ __align__(16) float g_sbuf[NN * NH];   // aggregation accumulator
__device__ float g_dinv[NN];                      // deg -> dinv (in place)
__device__ int   g_is64;                          // edge_index dtype flag

// ---------------------------------------------------------------------------
// Index fetch: dtype-agnostic (int32 vs int64, detected at runtime)
// ---------------------------------------------------------------------------
__device__ __forceinline__ int fetch_idx(const void* base, int half, int e, int is64) {
    if (is64) {
        const long long* p = (const long long*)base;
        return (int)p[(long long)half * NE + e];
    } else {
        const int* p = (const int*)base;
        return p[(long long)half * NE + e];
    }
}

__global__ void k_detect(const void* ei) {
    // int64 nonneg values < 2^31  =>  odd 32-bit words are all zero
    const unsigned* w = (const unsigned*)ei;
    unsigned acc = 0;
    for (int i = 0; i < 64; i++) acc |= w[2 * i + 1];
    g_is64 = (acc == 0) ? 1 : 0;
}

// ---------------------------------------------------------------------------
// Vectorized global reduction: red.global.add.v4.f32 (sm_90+)
// ---------------------------------------------------------------------------
__device__ __forceinline__ void red_add_v4(float* addr, float4 v) {
    asm volatile("red.global.add.v4.f32 [%0], {%1, %2, %3, %4};"
                 :: "l"(addr), "f"(v.x), "f"(v.y), "f"(v.z), "f"(v.w)
                 : "memory");
}

// ---------------------------------------------------------------------------
// Degree / dinv
// ---------------------------------------------------------------------------
__global__ void k_init_deg() {
    int i = blockIdx.x * blockDim.x + threadIdx.x;
    if (i < NN) g_dinv[i] = 1.0f;  // self loop
}

__global__ void k_count_deg(const void* __restrict__ ei) {
    int e = blockIdx.x * blockDim.x + threadIdx.x;
    if (e >= NE) return;
    int c = fetch_idx(ei, 1, e, g_is64);
    if ((unsigned)c < NN) atomicAdd(&g_dinv[c], 1.0f);
}

__global__ void k_rsqrt() {
    int i = blockIdx.x * blockDim.x + threadIdx.x;
    if (i < NN) g_dinv[i] = rsqrtf(g_dinv[i]);
}

// ---------------------------------------------------------------------------
// GEMM1: g[i,:] = (x[i,:] @ W1) * dinv[i]; also S init = g (self-loop term)
// ---------------------------------------------------------------------------
__global__ __launch_bounds__(128) void k_gemm1(const float* __restrict__ x,
                                               const float* __restrict__ W1) {
    __shared__ float W1s[NF * NH];          // 16 KB
    __shared__ float xs[128][33];           // padded, conflict-free

    int t = threadIdx.x;
    for (int i = t; i < NF * NH; i += 128) W1s[i] = W1[i];

    int node0 = blockIdx.x * 128;
    int node  = node0 + t;

    float4 a0 = {0,0,0,0}, a1 = {0,0,0,0}, a2 = {0,0,0,0}, a3 = {0,0,0,0};
    int c  = t & 31;
    int rb = t >> 5;

    for (int k0 = 0; k0 < NF; k0 += 32) {
        __syncthreads();
        #pragma unroll
        for (int i = 0; i < 32; i++) {
            int r = rb + 4 * i;            // covers rows 0..127
            int n = node0 + r;
            xs[r][c] = (n < NN) ? x[(long)n * NF + k0 + c] : 0.0f;
        }
        __syncthreads();
        #pragma unroll
        for (int k = 0; k < 32; k++) {
            float xv = xs[t][k];
            const float4* w = (const float4*)&W1s[(k0 + k) * NH];
            float4 w0 = w[0], w1 = w[1], w2 = w[2], w3 = w[3];
            a0.x += xv * w0.x; a0.y += xv * w0.y; a0.z += xv * w0.z; a0.w += xv * w0.w;
            a1.x += xv * w1.x; a1.y += xv * w1.y; a1.z += xv * w1.z; a1.w += xv * w1.w;
            a2.x += xv * w2.x; a2.y += xv * w2.y; a2.z += xv * w2.z; a2.w += xv * w2.w;
            a3.x += xv * w3.x; a3.y += xv * w3.y; a3.z += xv * w3.z; a3.w += xv * w3.w;
        }
    }

    if (node < NN) {
        float d = g_dinv[node];
        a0.x *= d; a0.y *= d; a0.z *= d; a0.w *= d;
        a1.x *= d; a1.y *= d; a1.z *= d; a1.w *= d;
        a2.x *= d; a2.y *= d; a2.z *= d; a2.w *= d;
        a3.x *= d; a3.y *= d; a3.z *= d; a3.w *= d;
        float4* gp = (float4*)&g_gbuf[node * NH];
        float4* sp = (float4*)&g_sbuf[node * NH];
        gp[0] = a0; gp[1] = a1; gp[2] = a2; gp[3] = a3;
        sp[0] = a0; sp[1] = a1; sp[2] = a2; sp[3] = a3;   // self-loop init
    }
}

// ---------------------------------------------------------------------------
// Edge scatter: S[col,:] += g[row,:]   (16 floats = 4x red.v4)
// ---------------------------------------------------------------------------
__global__ void k_scatter(const void* __restrict__ ei) {
    int e = blockIdx.x * blockDim.x + threadIdx.x;
    if (e >= NE) return;
    int is64 = g_is64;
    int r = fetch_idx(ei, 0, e, is64);
    int c = fetch_idx(ei, 1, e, is64);
    if ((unsigned)r >= NN || (unsigned)c >= NN) return;
    const float4* gp = (const float4*)&g_gbuf[r * NH];
    float4 v0 = __ldg(gp + 0), v1 = __ldg(gp + 1), v2 = __ldg(gp + 2), v3 = __ldg(gp + 3);
    float* sp = &g_sbuf[c * NH];
    red_add_v4(sp + 0,  v0);
    red_add_v4(sp + 4,  v1);
    red_add_v4(sp + 8,  v2);
    red_add_v4(sp + 12, v3);
}

// ---------------------------------------------------------------------------
// Mid: h = relu(dinv*S1 + b1); g2 = h*dinv; S2 init = g2
// ---------------------------------------------------------------------------
__global__ void k_mid(const float* __restrict__ b1) {
    int i = blockIdx.x * blockDim.x + threadIdx.x;
    if (i >= NN) return;
    float d = g_dinv[i];
    float4* sp = (float4*)&g_sbuf[i * NH];
    float4* gp = (float4*)&g_gbuf[i * NH];
    const float4* bp = (const float4*)b1;
    #pragma unroll
    for (int q = 0; q < 4; q++) {
        float4 s = sp[q];
        float4 b = __ldg(bp + q);
        float4 h;
        h.x = fmaxf(d * s.x + b.x, 0.0f) * d;
        h.y = fmaxf(d * s.y + b.y, 0.0f) * d;
        h.z = fmaxf(d * s.z + b.z, 0.0f) * d;
        h.w = fmaxf(d * s.w + b.w, 0.0f) * d;
        gp[q] = h;
        sp[q] = h;   // self-loop init
    }
}

// ---------------------------------------------------------------------------
// Epilogue: a = dinv*S2; logits = a @ W2 + b2; out = log_softmax(logits)
// ---------------------------------------------------------------------------
__global__ __launch_bounds__(128) void k_final(const float* __restrict__ W2,
                                               const float* __restrict__ b2,
                                               float* __restrict__ out) {
    __shared__ float W2s[NH * NH];
    __shared__ float b2s[NH];
    int t = threadIdx.x;
    for (int i = t; i < NH * NH; i += 128) W2s[i] = W2[i];
    if (t < NH) b2s[t] = b2[t];
    __syncthreads();

    int i = blockIdx.x * 128 + t;
    if (i >= NN) return;

    float d = g_dinv[i];
    const float4* sp = (const float4*)&g_sbuf[i * NH];
    float a[NH];
    #pragma unroll
    for (int q = 0; q < 4; q++) {
        float4 s = sp[q];
        a[q*4+0] = d * s.x; a[q*4+1] = d * s.y; a[q*4+2] = d * s.z; a[q*4+3] = d * s.w;
    }

    float l[NH];
    #pragma unroll
    for (int j = 0; j < NH; j++) l[j] = b2s[j];
    #pragma unroll
    for (int k = 0; k < NH; k++) {
        float ak = a[k];
        #pragma unroll
        for (int j = 0; j < NH; j++) l[j] += ak * W2s[k * NH + j];
    }

    float m = l[0];
    #pragma unroll
    for (int j = 1; j < NH; j++) m = fmaxf(m, l[j]);
    float s = 0.0f;
    #pragma unroll
    for (int j = 0; j < NH; j++) s += expf(l[j] - m);
    float lse = m + logf(s);

    float4* op = (float4*)&out[i * NH];
    #pragma unroll
    for (int q = 0; q < 4; q++) {
        float4 o;
        o.x = l[q*4+0] - lse; o.y = l[q*4+1] - lse;
        o.z = l[q*4+2] - lse; o.w = l[q*4+3] - lse;
        op[q] = o;
    }
}

// ---------------------------------------------------------------------------
// Launch — operands resolved BY SIZE; edge dtype detected on device.
//   x: 25,600,000 | edge_index: 6,400,000 | W1: 4096 | W2: 256 | b1,b2: 16
// ---------------------------------------------------------------------------
extern "C" void kernel_launch(void* const* d_in, const int* in_sizes, int n_in,
                              void* d_out, int out_size) {
    const float* x  = nullptr;
    const void*  ei = nullptr;
    const float* W1 = nullptr;
    const float* b1 = nullptr;
    const float* W2 = nullptr;
    const float* b2 = nullptr;

    for (int i = 0; i < n_in; i++) {
        int s = in_sizes[i];
        if      (s == NN * NF)  x  = (const float*)d_in[i];
        else if (s == 2 * NE)   ei = d_in[i];
        else if (s == NF * NH)  W1 = (const float*)d_in[i];
        else if (s == NH * NH)  W2 = (const float*)d_in[i];
        else if (s == NH) {
            if (!b1) b1 = (const float*)d_in[i];
            else     b2 = (const float*)d_in[i];
        }
    }
    if (!x || !ei || !W1 || !b1 || !W2 || !b2) return;

    float* out = (float*)d_out;

    int nb_nodes = (NN + 255) / 256;
    int nb_edges = (NE + 255) / 256;
    int nb_128   = (NN + 127) / 128;

    k_detect<<<1, 1>>>(ei);
    k_init_deg<<<nb_nodes, 256>>>();
    k_count_deg<<<nb_edges, 256>>>(ei);
    k_rsqrt<<<nb_nodes, 256>>>();
    k_gemm1<<<nb_128, 128>>>(x, W1);
    k_scatter<<<nb_edges, 256>>>(ei);
    k_mid<<<nb_nodes, 256>>>(b1);
    k_scatter<<<nb_edges, 256>>>(ei);
    k_final<<<nb_128, 128>>>(W2, b2, out);
}

// round 4
// speedup vs baseline: 1.0996x; 1.0996x over previous
#include <cuda_runtime.h>

#define NN 100000
#define NE 3200000
#define NF 256
#define NH 16

#define SCAN_B 512
#define NBLK ((NN + SCAN_B - 1) / SCAN_B)   // 196

// Scratch (__device__ globals — no runtime allocation)
__device__ __align__(16) float g_gbuf[NN * NH];   // per-node message features (g = h*dinv)
__device__ __align__(16) float g_sbuf[NN * NH];   // aggregation result
__device__ float g_dinv[NN];
__device__ int   g_degi[NN];                      // edge-in-degree (no self loop)
__device__ int   g_rowptr[NN];                    // CSR start offsets
__device__ int   g_cursor[NN];                    // fill cursors
__device__ int   g_partial[NBLK];
__device__ int   g_adj[NE];                       // CSR adjacency (source node ids)
__device__ int   g_is64;

// ---------------------------------------------------------------------------
// Index fetch: dtype-agnostic (int32 vs int64, detected at runtime)
// ---------------------------------------------------------------------------
__device__ __forceinline__ int fetch_idx(const void* base, int half, int e, int is64) {
    if (is64) {
        const long long* p = (const long long*)base;
        return (int)p[(long long)half * NE + e];
    } else {
        const int* p = (const int*)base;
        return p[(long long)half * NE + e];
    }
}

__global__ void k_detect(const void* ei) {
    const unsigned* w = (const unsigned*)ei;
    unsigned acc = 0;
    for (int i = 0; i < 64; i++) acc |= w[2 * i + 1];
    g_is64 = (acc == 0) ? 1 : 0;
}

// ---------------------------------------------------------------------------
// CSR build
// ---------------------------------------------------------------------------
__global__ void k_zero() {
    int i = blockIdx.x * blockDim.x + threadIdx.x;
    if (i < NN) g_degi[i] = 0;
}

__global__ void k_hist(const void* __restrict__ ei) {
    int e = blockIdx.x * blockDim.x + threadIdx.x;
    if (e >= NE) return;
    int c = fetch_idx(ei, 1, e, g_is64);
    if ((unsigned)c < NN) atomicAdd(&g_degi[c], 1);
}

__global__ void k_rsqrt() {
    int i = blockIdx.x * blockDim.x + threadIdx.x;
    if (i < NN) g_dinv[i] = rsqrtf((float)(g_degi[i] + 1));   // +1 self loop
}

// block sums of degree
__global__ __launch_bounds__(SCAN_B) void k_scan1() {
    __shared__ int sh[SCAN_B];
    int i = blockIdx.x * SCAN_B + threadIdx.x;
    sh[threadIdx.x] = (i < NN) ? g_degi[i] : 0;
    __syncthreads();
    for (int s = SCAN_B / 2; s > 0; s >>= 1) {
        if (threadIdx.x < s) sh[threadIdx.x] += sh[threadIdx.x + s];
        __syncthreads();
    }
    if (threadIdx.x == 0) g_partial[blockIdx.x] = sh[0];
}

// exclusive scan of block sums (NBLK <= 256)
__global__ __launch_bounds__(256) void k_scan2() {
    __shared__ int sh[256];
    int t = threadIdx.x;
    int v = (t < NBLK) ? g_partial[t] : 0;
    sh[t] = v;
    __syncthreads();
    #pragma unroll
    for (int off = 1; off < 256; off <<= 1) {
        int add = (t >= off) ? sh[t - off] : 0;
        __syncthreads();
        sh[t] += add;
        __syncthreads();
    }
    if (t < NBLK) g_partial[t] = sh[t] - v;   // exclusive
}

// per-element exclusive scan + block offset -> rowptr, cursor
__global__ __launch_bounds__(SCAN_B) void k_scan3() {
    __shared__ int sh[SCAN_B];
    int i = blockIdx.x * SCAN_B + threadIdx.x;
    int t = threadIdx.x;
    int v = (i < NN) ? g_degi[i] : 0;
    sh[t] = v;
    __syncthreads();
    #pragma unroll
    for (int off = 1; off < SCAN_B; off <<= 1) {
        int add = (t >= off) ? sh[t - off] : 0;
        __syncthreads();
        sh[t] += add;
        __syncthreads();
    }
    if (i < NN) {
        int start = sh[t] - v + g_partial[blockIdx.x];
        g_rowptr[i] = start;
        g_cursor[i] = start;
    }
}

__global__ void k_fill(const void* __restrict__ ei) {
    int e = blockIdx.x * blockDim.x + threadIdx.x;
    if (e >= NE) return;
    int is64 = g_is64;
    int r = fetch_idx(ei, 0, e, is64);
    int c = fetch_idx(ei, 1, e, is64);
    if ((unsigned)r >= NN || (unsigned)c >= NN) return;
    int pos = atomicAdd(&g_cursor[c], 1);
    g_adj[pos] = r;
}

// ---------------------------------------------------------------------------
// GEMM1: g[i,:] = (x[i,:] @ W1) * dinv[i]
// ---------------------------------------------------------------------------
__global__ __launch_bounds__(128) void k_gemm1(const float* __restrict__ x,
                                               const float* __restrict__ W1) {
    __shared__ float W1s[NF * NH];          // 16 KB
    __shared__ float xs[128][33];

    int t = threadIdx.x;
    for (int i = t; i < NF * NH; i += 128) W1s[i] = W1[i];

    int node0 = blockIdx.x * 128;
    int node  = node0 + t;

    float4 a0 = {0,0,0,0}, a1 = {0,0,0,0}, a2 = {0,0,0,0}, a3 = {0,0,0,0};
    int c  = t & 31;
    int rb = t >> 5;

    for (int k0 = 0; k0 < NF; k0 += 32) {
        __syncthreads();
        #pragma unroll
        for (int i = 0; i < 32; i++) {
            int r = rb + 4 * i;
            int n = node0 + r;
            xs[r][c] = (n < NN) ? x[(long)n * NF + k0 + c] : 0.0f;
        }
        __syncthreads();
        #pragma unroll
        for (int k = 0; k < 32; k++) {
            float xv = xs[t][k];
            const float4* w = (const float4*)&W1s[(k0 + k) * NH];
            float4 w0 = w[0], w1 = w[1], w2 = w[2], w3 = w[3];
            a0.x += xv * w0.x; a0.y += xv * w0.y; a0.z += xv * w0.z; a0.w += xv * w0.w;
            a1.x += xv * w1.x; a1.y += xv * w1.y; a1.z += xv * w1.z; a1.w += xv * w1.w;
            a2.x += xv * w2.x; a2.y += xv * w2.y; a2.z += xv * w2.z; a2.w += xv * w2.w;
            a3.x += xv * w3.x; a3.y += xv * w3.y; a3.z += xv * w3.z; a3.w += xv * w3.w;
        }
    }

    if (node < NN) {
        float d = g_dinv[node];
        a0.x *= d; a0.y *= d; a0.z *= d; a0.w *= d;
        a1.x *= d; a1.y *= d; a1.z *= d; a1.w *= d;
        a2.x *= d; a2.y *= d; a2.z *= d; a2.w *= d;
        a3.x *= d; a3.y *= d; a3.z *= d; a3.w *= d;
        float4* gp = (float4*)&g_gbuf[node * NH];
        gp[0] = a0; gp[1] = a1; gp[2] = a2; gp[3] = a3;
    }
}

// ---------------------------------------------------------------------------
// CSR aggregation: S[i,:] = g[i,:] + sum_{r in adj(i)} g[r,:]
// 16 lanes per node (lane = feature); adj read coalesced, shfl-broadcast.
// ---------------------------------------------------------------------------
__global__ __launch_bounds__(256) void k_agg() {
    int t = threadIdx.x;
    int f = t & 15;
    int node = blockIdx.x * 16 + (t >> 4);
    if (node >= NN) return;

    int start = g_rowptr[node];
    int cnt   = g_degi[node];
    int end   = start + cnt;

    float acc = g_gbuf[node * NH + f];   // self loop

    for (int j0 = start; j0 < end; j0 += 16) {
        int jl = j0 + f;
        int rl = (jl < end) ? g_adj[jl] : -1;
        int rem = end - j0;
        int lim = rem < 16 ? rem : 16;
        #pragma unroll
        for (int u = 0; u < 16; u++) {
            if (u >= lim) break;
            int r = __shfl_sync(0xffffffffu, rl, u, 16);
            acc += __ldg(&g_gbuf[r * NH + f]);
        }
    }
    g_sbuf[node * NH + f] = acc;
}

// ---------------------------------------------------------------------------
// Mid: h = relu(dinv*S1 + b1); g2 = h*dinv
// ---------------------------------------------------------------------------
__global__ void k_mid(const float* __restrict__ b1) {
    int i = blockIdx.x * blockDim.x + threadIdx.x;
    if (i >= NN) return;
    float d = g_dinv[i];
    const float4* sp = (const float4*)&g_sbuf[i * NH];
    float4*       gp = (float4*)&g_gbuf[i * NH];
    const float4* bp = (const float4*)b1;
    #pragma unroll
    for (int q = 0; q < 4; q++) {
        float4 s = sp[q];
        float4 b = __ldg(bp + q);
        float4 h;
        h.x = fmaxf(d * s.x + b.x, 0.0f) * d;
        h.y = fmaxf(d * s.y + b.y, 0.0f) * d;
        h.z = fmaxf(d * s.z + b.z, 0.0f) * d;
        h.w = fmaxf(d * s.w + b.w, 0.0f) * d;
        gp[q] = h;
    }
}

// ---------------------------------------------------------------------------
// Epilogue: a = dinv*S2; logits = a @ W2 + b2; out = log_softmax
// ---------------------------------------------------------------------------
__global__ __launch_bounds__(128) void k_final(const float* __restrict__ W2,
                                               const float* __restrict__ b2,
                                               float* __restrict__ out) {
    __shared__ float W2s[NH * NH];
    __shared__ float b2s[NH];
    int t = threadIdx.x;
    for (int i = t; i < NH * NH; i += 128) W2s[i] = W2[i];
    if (t < NH) b2s[t] = b2[t];
    __syncthreads();

    int i = blockIdx.x * 128 + t;
    if (i >= NN) return;

    float d = g_dinv[i];
    const float4* sp = (const float4*)&g_sbuf[i * NH];
    float a[NH];
    #pragma unroll
    for (int q = 0; q < 4; q++) {
        float4 s = sp[q];
        a[q*4+0] = d * s.x; a[q*4+1] = d * s.y; a[q*4+2] = d * s.z; a[q*4+3] = d * s.w;
    }

    float l[NH];
    #pragma unroll
    for (int j = 0; j < NH; j++) l[j] = b2s[j];
    #pragma unroll
    for (int k = 0; k < NH; k++) {
        float ak = a[k];
        #pragma unroll
        for (int j = 0; j < NH; j++) l[j] += ak * W2s[k * NH + j];
    }

    float m = l[0];
    #pragma unroll
    for (int j = 1; j < NH; j++) m = fmaxf(m, l[j]);
    float s = 0.0f;
    #pragma unroll
    for (int j = 0; j < NH; j++) s += expf(l[j] - m);
    float lse = m + logf(s);

    float4* op = (float4*)&out[i * NH];
    #pragma unroll
    for (int q = 0; q < 4; q++) {
        float4 o;
        o.x = l[q*4+0] - lse; o.y = l[q*4+1] - lse;
        o.z = l[q*4+2] - lse; o.w = l[q*4+3] - lse;
        op[q] = o;
    }
}

// ---------------------------------------------------------------------------
// Launch
// ---------------------------------------------------------------------------
extern "C" void kernel_launch(void* const* d_in, const int* in_sizes, int n_in,
                              void* d_out, int out_size) {
    const float* x  = nullptr;
    const void*  ei = nullptr;
    const float* W1 = nullptr;
    const float* b1 = nullptr;
    const float* W2 = nullptr;
    const float* b2 = nullptr;

    for (int i = 0; i < n_in; i++) {
        int s = in_sizes[i];
        if      (s == NN * NF)  x  = (const float*)d_in[i];
        else if (s == 2 * NE)   ei = d_in[i];
        else if (s == NF * NH)  W1 = (const float*)d_in[i];
        else if (s == NH * NH)  W2 = (const float*)d_in[i];
        else if (s == NH) {
            if (!b1) b1 = (const float*)d_in[i];
            else     b2 = (const float*)d_in[i];
        }
    }
    if (!x || !ei || !W1 || !b1 || !W2 || !b2) return;

    float* out = (float*)d_out;

    int nb_nodes = (NN + 255) / 256;
    int nb_edges = (NE + 255) / 256;
    int nb_128   = (NN + 127) / 128;
    int nb_agg   = (NN + 15) / 16;

    k_detect<<<1, 1>>>(ei);
    k_zero  <<<nb_nodes, 256>>>();
    k_hist  <<<nb_edges, 256>>>(ei);
    k_rsqrt <<<nb_nodes, 256>>>();
    k_scan1 <<<NBLK, SCAN_B>>>();
    k_scan2 <<<1, 256>>>();
    k_scan3 <<<NBLK, SCAN_B>>>();
    k_fill  <<<nb_edges, 256>>>(ei);
    k_gemm1 <<<nb_128, 128>>>(x, W1);
    k_agg   <<<nb_agg, 256>>>();
    k_mid   <<<nb_nodes, 256>>>(b1);
    k_agg   <<<nb_agg, 256>>>();
    k_final <<<nb_128, 128>>>(W2, b2, out);
}